// round 1
// baseline (speedup 1.0000x reference)
#include <cuda_runtime.h>

#define N_ROWS 8192
#define F_DIM  512
#define H1_DIM 512
#define SU_DIM 256
#define T_STEPS 16
#define BETA_F 0.95f
#define THR_F  1.0f

// ---------------- scratch (static device globals; no allocations) ----------------
__device__ float    g_cur0[N_ROWS * H1_DIM];                   // 16 MB
__device__ unsigned g_spk1[N_ROWS * T_STEPS * (H1_DIM / 32)];  // 8 MB  [n][t][w]
__device__ float    g_sf[N_ROWS * SU_DIM];                     // 8 MB
__device__ float    g_W2T[H1_DIM * SU_DIM];                    // [j][i]
__device__ float    g_WeffT[SU_DIM * F_DIM];                   // [i][f]
__device__ float    g_beff[F_DIM];

// ---------------- small prep kernels ----------------
__global__ __launch_bounds__(256) void k_w2t(const float* __restrict__ W2) {
    int idx = blockIdx.x * 256 + threadIdx.x;   // idx < 256*512
    int i = idx >> 9;
    int j = idx & 511;
    g_W2T[j * SU_DIM + i] = W2[idx];
}

// WeffT[i][f] = sum_l Wfu[f][l] * Wf[l][i] + Wfu[f][256+i]
__global__ __launch_bounds__(256) void k_wefft(const float* __restrict__ Wfu,
                                               const float* __restrict__ Wf) {
    __shared__ float wrow[256];
    int f = blockIdx.x;          // 0..511
    int i = threadIdx.x;         // 0..255
    wrow[i] = Wfu[f * 512 + i];
    __syncthreads();
    float acc = Wfu[f * 512 + 256 + i];
#pragma unroll 4
    for (int l = 0; l < 256; l++)
        acc = fmaf(wrow[l], Wf[l * 256 + i], acc);
    g_WeffT[i * 512 + f] = acc;
}

// beff[f] = sum_l Wfu[f][l]*bf[l] + bfu[f]
__global__ __launch_bounds__(512) void k_beff(const float* __restrict__ Wfu,
                                              const float* __restrict__ bf,
                                              const float* __restrict__ bfu) {
    int f = threadIdx.x;  // 512 threads, 1 block
    float acc = bfu[f];
#pragma unroll 4
    for (int l = 0; l < 256; l++)
        acc = fmaf(Wfu[f * 512 + l], bf[l], acc);
    g_beff[f] = acc;
}

// ---------------- K1: cur0 = X @ W1^T + b1  (fp32 tiled GEMM, NT form) ----------------
#define K1_BM 128
#define K1_BN 128
#define K1_BK 16
#define K1_LDS 136

__global__ __launch_bounds__(256) void k_gemm1(const float* __restrict__ X,
                                               const float* __restrict__ W1,
                                               const float* __restrict__ b1) {
    __shared__ float As[K1_BK][K1_LDS];
    __shared__ float Bs[K1_BK][K1_LDS];

    const int n0 = blockIdx.y * K1_BM;
    const int h0 = blockIdx.x * K1_BN;
    const int tid = threadIdx.x;
    const int ty = tid >> 4;        // 0..15 -> row group
    const int tx = tid & 15;        // 0..15 -> col group

    float acc[8][8];
#pragma unroll
    for (int i = 0; i < 8; i++)
#pragma unroll
        for (int j = 0; j < 8; j++) acc[i][j] = 0.f;

    for (int k0 = 0; k0 < 512; k0 += K1_BK) {
#pragma unroll
        for (int p = 0; p < 2; p++) {
            int q = tid + p * 256;          // float4 tile index (512 total per operand)
            int row = q >> 2;
            int kq = q & 3;
            float4 av = *(const float4*)(X + (size_t)(n0 + row) * 512 + k0 + kq * 4);
            As[kq * 4 + 0][row] = av.x;
            As[kq * 4 + 1][row] = av.y;
            As[kq * 4 + 2][row] = av.z;
            As[kq * 4 + 3][row] = av.w;
            float4 bv = *(const float4*)(W1 + (size_t)(h0 + row) * 512 + k0 + kq * 4);
            Bs[kq * 4 + 0][row] = bv.x;
            Bs[kq * 4 + 1][row] = bv.y;
            Bs[kq * 4 + 2][row] = bv.z;
            Bs[kq * 4 + 3][row] = bv.w;
        }
        __syncthreads();
#pragma unroll
        for (int k = 0; k < K1_BK; k++) {
            float a[8], b[8];
            *(float4*)(a)     = *(const float4*)&As[k][ty * 8];
            *(float4*)(a + 4) = *(const float4*)&As[k][ty * 8 + 4];
            *(float4*)(b)     = *(const float4*)&Bs[k][tx * 8];
            *(float4*)(b + 4) = *(const float4*)&Bs[k][tx * 8 + 4];
#pragma unroll
            for (int i = 0; i < 8; i++)
#pragma unroll
                for (int j = 0; j < 8; j++)
                    acc[i][j] = fmaf(a[i], b[j], acc[i][j]);
        }
        __syncthreads();
    }

    float bv[8];
#pragma unroll
    for (int j = 0; j < 8; j++) bv[j] = b1[h0 + tx * 8 + j];

#pragma unroll
    for (int i = 0; i < 8; i++) {
        float4 o0, o1;
        o0.x = acc[i][0] + bv[0]; o0.y = acc[i][1] + bv[1];
        o0.z = acc[i][2] + bv[2]; o0.w = acc[i][3] + bv[3];
        o1.x = acc[i][4] + bv[4]; o1.y = acc[i][5] + bv[5];
        o1.z = acc[i][6] + bv[6]; o1.w = acc[i][7] + bv[7];
        size_t base = (size_t)(n0 + ty * 8 + i) * 512 + h0 + tx * 8;
        *(float4*)(g_cur0 + base)     = o0;
        *(float4*)(g_cur0 + base + 4) = o1;
    }
}

// ---------------- K2: precompute spk1 bitmasks for all 16 steps ----------------
__global__ __launch_bounds__(256) void k_spk1(const float* __restrict__ b1) {
    int idx = blockIdx.x * 256 + threadIdx.x;   // n*512 + j
    int n = idx >> 9;
    int j = idx & 511;
    int lane = threadIdx.x & 31;

    float c0 = g_cur0[idx];
    float bj = b1[j];
    float mem = 0.f;
    float spk = 0.f;
    unsigned myword = 0;
#pragma unroll
    for (int t = 0; t < T_STEPS; t++) {
        float cur = (t == 0) ? c0 : bj;
        mem = fmaf(BETA_F, mem, cur) - spk;
        bool s = (mem - THR_F) > 0.f;
        spk = s ? THR_F : 0.f;
        unsigned w = __ballot_sync(0xffffffffu, s);
        if (lane == t) myword = w;
    }
    if (lane < 16) {
        int w = j >> 5;   // warp-uniform word index 0..15
        g_spk1[((size_t)n * 16 + lane) * 16 + w] = myword;
    }
}

// ---------------- K3: sparse spike-driven layer-2 loop -> spike_features ----------------
// Block: 256 threads (thread = output neuron i), 16 rows per block.
__global__ __launch_bounds__(256) void k_spike2(const float* __restrict__ b2) {
    __shared__ unsigned masks[16][16];   // [row][word]
    const int i = threadIdx.x;
    const int n0 = blockIdx.x * 16;
    const float b2i = b2[i];

    float mem2[16], cnt[16];
#pragma unroll
    for (int r = 0; r < 16; r++) { mem2[r] = 0.f; cnt[r] = 0.f; }
    unsigned spkprev = 0;

    for (int t = 0; t < T_STEPS; t++) {
        __syncthreads();
        {
            int row = i >> 4, w = i & 15;
            masks[row][w] = g_spk1[((size_t)(n0 + row) * 16 + t) * 16 + w];
        }
        __syncthreads();

#pragma unroll
        for (int r = 0; r < 16; r++) {
            float cur = b2i;
#pragma unroll 1
            for (int w = 0; w < 16; w++) {
                unsigned m = masks[r][w];          // warp-uniform broadcast
                while (m) {
                    int b = __ffs(m) - 1;
                    m &= m - 1;
                    cur += __ldg(&g_W2T[(size_t)(w * 32 + b) * SU_DIM + i]);  // coalesced
                }
            }
            float mm = fmaf(BETA_F, mem2[r], cur) - (((spkprev >> r) & 1u) ? THR_F : 0.f);
            mem2[r] = mm;
            bool s = (mm - THR_F) > 0.f;
            spkprev = (spkprev & ~(1u << r)) | ((unsigned)s << r);
            cnt[r] += s ? 1.f : 0.f;
        }
    }

#pragma unroll
    for (int r = 0; r < 16; r++)
        g_sf[(size_t)(n0 + r) * SU_DIM + i] = cnt[r] * (1.f / 16.f);
}

// ---------------- K4: y = sf @ Weff^T + beff, LayerNorm, ReLU ----------------
// Block: 256 threads = 8 warps; 32 rows per block; warp owns 4 rows x full 512 cols.
__global__ __launch_bounds__(256) void k_final(const float* __restrict__ ln_g,
                                               const float* __restrict__ ln_b,
                                               float* __restrict__ out) {
    __shared__ float Wc[16][512];    // 32 KB   chunk of WeffT
    __shared__ float sfc[32][16];    // 2 KB

    const int tid = threadIdx.x;
    const int warp = tid >> 5;
    const int lane = tid & 31;
    const int n0 = blockIdx.x * 32;

    float acc[4][16];
#pragma unroll
    for (int r = 0; r < 4; r++)
#pragma unroll
        for (int kk = 0; kk < 16; kk++) acc[r][kk] = 0.f;

    for (int ic = 0; ic < 256; ic += 16) {
        __syncthreads();
#pragma unroll
        for (int p = 0; p < 8; p++) {
            int e4 = tid + p * 256;                 // 2048 float4 total
            int idx = e4 * 4;
            int ii = idx >> 9;
            int f = idx & 511;
            *(float4*)&Wc[ii][f] = *(const float4*)&g_WeffT[(size_t)(ic + ii) * 512 + f];
        }
#pragma unroll
        for (int p = 0; p < 2; p++) {
            int e = tid + p * 256;
            int row = e >> 4, ii = e & 15;
            sfc[row][ii] = g_sf[(size_t)(n0 + row) * 256 + ic + ii];
        }
        __syncthreads();

#pragma unroll
        for (int ii = 0; ii < 16; ii++) {
            float w[16];
#pragma unroll
            for (int kk = 0; kk < 16; kk++) w[kk] = Wc[ii][lane + 32 * kk];
            float a0 = sfc[warp * 4 + 0][ii];
            float a1 = sfc[warp * 4 + 1][ii];
            float a2 = sfc[warp * 4 + 2][ii];
            float a3 = sfc[warp * 4 + 3][ii];
#pragma unroll
            for (int kk = 0; kk < 16; kk++) {
                acc[0][kk] = fmaf(a0, w[kk], acc[0][kk]);
                acc[1][kk] = fmaf(a1, w[kk], acc[1][kk]);
                acc[2][kk] = fmaf(a2, w[kk], acc[2][kk]);
                acc[3][kk] = fmaf(a3, w[kk], acc[3][kk]);
            }
        }
    }

    float be[16], gg[16], bb[16];
#pragma unroll
    for (int kk = 0; kk < 16; kk++) {
        int f = lane + 32 * kk;
        be[kk] = g_beff[f];
        gg[kk] = ln_g[f];
        bb[kk] = ln_b[f];
    }

#pragma unroll
    for (int r = 0; r < 4; r++) {
        float y[16];
        float s = 0.f;
#pragma unroll
        for (int kk = 0; kk < 16; kk++) {
            y[kk] = acc[r][kk] + be[kk];
            s += y[kk];
        }
#pragma unroll
        for (int o = 16; o > 0; o >>= 1) s += __shfl_xor_sync(0xffffffffu, s, o);
        float mu = s * (1.f / 512.f);
        float sq = 0.f;
#pragma unroll
        for (int kk = 0; kk < 16; kk++) {
            float d = y[kk] - mu;
            sq = fmaf(d, d, sq);
        }
#pragma unroll
        for (int o = 16; o > 0; o >>= 1) sq += __shfl_xor_sync(0xffffffffu, sq, o);
        float rinv = rsqrtf(sq * (1.f / 512.f) + 1e-5f);

        int n = n0 + warp * 4 + r;
#pragma unroll
        for (int kk = 0; kk < 16; kk++) {
            float v = fmaf((y[kk] - mu) * rinv, gg[kk], bb[kk]);
            out[(size_t)n * 512 + lane + 32 * kk] = fmaxf(v, 0.f);
        }
    }
}

// ---------------- launch ----------------
extern "C" void kernel_launch(void* const* d_in, const int* in_sizes, int n_in,
                              void* d_out, int out_size) {
    const float* x    = (const float*)d_in[0];
    const float* W1   = (const float*)d_in[1];
    const float* b1   = (const float*)d_in[2];
    const float* W2   = (const float*)d_in[3];
    const float* b2   = (const float*)d_in[4];
    const float* Wf   = (const float*)d_in[5];
    const float* bf   = (const float*)d_in[6];
    const float* Wfu  = (const float*)d_in[7];
    const float* bfu  = (const float*)d_in[8];
    const float* ln_g = (const float*)d_in[9];
    const float* ln_b = (const float*)d_in[10];
    float* out = (float*)d_out;

    k_w2t<<<(SU_DIM * H1_DIM) / 256, 256>>>(W2);
    k_wefft<<<F_DIM, 256>>>(Wfu, Wf);
    k_beff<<<1, 512>>>(Wfu, bf, bfu);
    k_gemm1<<<dim3(H1_DIM / K1_BN, N_ROWS / K1_BM), 256>>>(x, W1, b1);
    k_spk1<<<(N_ROWS * H1_DIM) / 256, 256>>>(b1);
    k_spike2<<<N_ROWS / 16, 256>>>(b2);
    k_final<<<N_ROWS / 32, 256>>>(ln_g, ln_b, out);
}